// round 7
// baseline (speedup 1.0000x reference)
#include <cuda_runtime.h>

#define CIN  3
#define COUT 16
#define OD   62
#define OH   62
#define OW   62

typedef unsigned long long ull;

__device__ __forceinline__ void fma2(ull& acc, ull x, ull w) {
    asm("fma.rn.f32x2 %0, %1, %2, %0;" : "+l"(acc) : "l"(x), "l"(w));
}
__device__ __forceinline__ ull rep2(float a) {
    ull r;
    asm("mov.b64 %0, {%1, %1};" : "=l"(r) : "f"(a));
    return r;
}
__device__ __forceinline__ float2 unpk(ull v) {
    float2 r;
    asm("mov.b64 {%0, %1}, %2;" : "=f"(r.x), "=f"(r.y) : "l"(v));
    return r;
}

// Fused Conv3d(3->16,k=3,valid) + bias + min over D + softmax over C.
// One thread = (n, h', w', channel-group of 8). f32x2 accumulators over
// channel pairs, depth tile of 4. The 9 (ci,kh) bodies are FULLY unrolled
// (compile-time addresses) so ptxas can software-pipeline each body's
// LDG/LDS under the previous body's FMA block.
__global__ __launch_bounds__(128, 4)
void fused_conv_min_softmax(const float* __restrict__ x,
                            const float* __restrict__ wgt,
                            const float* __restrict__ bias,
                            float* __restrict__ out)
{
    // Weights transposed to [pos(81)][c(16)]; adjacent channels = f32x2 pairs.
    __shared__ ull   wsp[81 * 8];
    __shared__ float bsh[16];
    __shared__ float sred[2][64];
    float* wsf = (float*)wsp;

    const int tid = threadIdx.x;
    for (int i = tid; i < 81 * 16; i += 128) {
        const int c   = i & 15;
        const int pos = i >> 4;
        wsf[i] = wgt[c * 81 + pos];
    }
    if (tid < 16) bsh[tid] = bias[tid];
    __syncthreads();

    const int cg = tid >> 6;          // channel group 0/1 (channels cg*8..+7)
    const int wl = tid & 63;          // lane-w
    const bool active = (wl < OW);
    const int w = active ? wl : 0;    // clamp for safe addressing

    const int h = blockIdx.x;         // 0..61
    const int n = blockIdx.y;         // 0..15

    float mval[8];
#pragma unroll
    for (int c = 0; c < 8; c++) mval[c] = 3.402823466e38f;

    // x layout [ci][d][y][w]: strides 262144 / 4096 / 64
    const float* xbase = x + (size_t)n * (CIN * 262144) + h * 64 + w;
    const ull* wcg = &wsp[cg * 4];

    // 16 depth tiles of 4: d0 = 0,4,...,56, then 58 (overlap; min idempotent)
#pragma unroll 1
    for (int t = 0; t < 16; t++) {
        const int d0 = (t < 15) ? (t << 2) : 58;
        const float* xt = xbase + d0 * 4096;

        ull acc[4][4];
#pragma unroll
        for (int d = 0; d < 4; d++)
#pragma unroll
            for (int pr = 0; pr < 4; pr++) acc[d][pr] = 0ull;

        // FULLY unrolled: 9 bodies, all offsets compile-time.
#pragma unroll
        for (int ci = 0; ci < CIN; ci++) {
#pragma unroll
            for (int kh = 0; kh < 3; kh++) {
                const float* rp0 = xt + ci * 262144 + kh * 64;

                // 6 input-depth rows cover kd(0..2) x depth-tile(0..3)
                ull xr[6][3];
#pragma unroll
                for (int r = 0; r < 6; r++) {
                    const float* rp = rp0 + r * 4096;
                    xr[r][0] = rep2(rp[0]);
                    xr[r][1] = rep2(rp[1]);
                    xr[r][2] = rep2(rp[2]);
                }

#pragma unroll
                for (int kd = 0; kd < 3; kd++) {
#pragma unroll
                    for (int kw = 0; kw < 3; kw++) {
                        const int pos = ci * 27 + kd * 9 + kh * 3 + kw;
                        const ull* wrow = &wcg[pos * 8];
#pragma unroll
                        for (int pr = 0; pr < 4; pr++) {
                            const ull wv = wrow[pr];
                            fma2(acc[0][pr], xr[kd + 0][kw], wv);
                            fma2(acc[1][pr], xr[kd + 1][kw], wv);
                            fma2(acc[2][pr], xr[kd + 2][kw], wv);
                            fma2(acc[3][pr], xr[kd + 3][kw], wv);
                        }
                    }
                }
            }
        }

#pragma unroll
        for (int d = 0; d < 4; d++)
#pragma unroll
            for (int pr = 0; pr < 4; pr++) {
                const float2 v = unpk(acc[d][pr]);
                mval[2 * pr]     = fminf(mval[2 * pr],     v.x);
                mval[2 * pr + 1] = fminf(mval[2 * pr + 1], v.y);
            }
    }

    // bias + softmax over 16 channels, split across 2 threads (cg 0/1)
    float v[8];
    float mx = -3.402823466e38f;
#pragma unroll
    for (int c = 0; c < 8; c++) {
        v[c] = mval[c] + bsh[cg * 8 + c];
        mx = fmaxf(mx, v[c]);
    }
    sred[cg][wl] = mx;
    __syncthreads();
    mx = fmaxf(sred[0][wl], sred[1][wl]);
    __syncthreads();

    float s = 0.f;
#pragma unroll
    for (int c = 0; c < 8; c++) {
        v[c] = __expf(v[c] - mx);
        s += v[c];
    }
    sred[cg][wl] = s;
    __syncthreads();
    const float inv = 1.0f / (sred[0][wl] + sred[1][wl]);

    if (active) {
        const int hw = h * OW + w;
#pragma unroll
        for (int c = 0; c < 8; c++) {
            out[(size_t)(n * COUT + cg * 8 + c) * (OH * OW) + hw] = v[c] * inv;
        }
    }
}

extern "C" void kernel_launch(void* const* d_in, const int* in_sizes, int n_in,
                              void* d_out, int out_size)
{
    const float* x    = (const float*)d_in[0];  // [16,3,64,64,64]
    const float* wgt  = (const float*)d_in[1];  // [16,3,3,3,3]
    const float* bias = (const float*)d_in[2];  // [16]
    float* out = (float*)d_out;                 // [16,16,62,62]

    dim3 grid(OH, 16);   // (h', n)
    dim3 block(128);     // 64 w-lanes x 2 channel groups
    fused_conv_min_softmax<<<grid, block>>>(x, wgt, bias, out);
}

// round 8
// speedup vs baseline: 6.5382x; 6.5382x over previous
#include <cuda_runtime.h>

#define CIN  3
#define COUT 16
#define OD   62
#define OH   62
#define OW   62

typedef unsigned long long ull;

__device__ __forceinline__ void fma2(ull& acc, ull x, ull w) {
    asm("fma.rn.f32x2 %0, %1, %2, %0;" : "+l"(acc) : "l"(x), "l"(w));
}
__device__ __forceinline__ ull rep2(float a) {
    ull r;
    asm("mov.b64 %0, {%1, %1};" : "=l"(r) : "f"(a));
    return r;
}
__device__ __forceinline__ float2 unpk(ull v) {
    float2 r;
    asm("mov.b64 {%0, %1}, %2;" : "=f"(r.x), "=f"(r.y) : "l"(v));
    return r;
}

// Fused Conv3d(3->16,k=3,valid) + bias + min over D + softmax over C.
// One thread = (n, h', w', channel-group of 8). f32x2 accumulators over
// channel pairs, depth tile of 4. kh bodies (3) unrolled so ptxas overlaps
// each body's LDG/LDS with the previous body's FMA block; ci stays rolled
// to bound register pressure (R7 showed full unroll spills).
__global__ __launch_bounds__(128, 4)
void fused_conv_min_softmax(const float* __restrict__ x,
                            const float* __restrict__ wgt,
                            const float* __restrict__ bias,
                            float* __restrict__ out)
{
    // Weights transposed to [pos(81)][c(16)]; adjacent channels = f32x2 pairs.
    __shared__ ull   wsp[81 * 8];
    __shared__ float bsh[16];
    __shared__ float sred[2][64];
    float* wsf = (float*)wsp;

    const int tid = threadIdx.x;
    for (int i = tid; i < 81 * 16; i += 128) {
        const int c   = i & 15;
        const int pos = i >> 4;
        wsf[i] = wgt[c * 81 + pos];
    }
    if (tid < 16) bsh[tid] = bias[tid];
    __syncthreads();

    const int cg = tid >> 6;          // channel group 0/1 (channels cg*8..+7)
    const int wl = tid & 63;          // lane-w
    const bool active = (wl < OW);
    const int w = active ? wl : 0;    // clamp for safe addressing

    const int h = blockIdx.x;         // 0..61
    const int n = blockIdx.y;         // 0..15

    float mval[8];
#pragma unroll
    for (int c = 0; c < 8; c++) mval[c] = 3.402823466e38f;

    // x layout [ci][d][y][w]: strides 262144 / 4096 / 64
    const float* xbase = x + (size_t)n * (CIN * 262144) + h * 64 + w;
    const ull* wcg = &wsp[cg * 4];

    // 16 depth tiles of 4: d0 = 0,4,...,56, then 58 (overlap; min idempotent)
#pragma unroll 1
    for (int t = 0; t < 16; t++) {
        const int d0 = (t < 15) ? (t << 2) : 58;

        ull acc[4][4];
#pragma unroll
        for (int d = 0; d < 4; d++)
#pragma unroll
            for (int pr = 0; pr < 4; pr++) acc[d][pr] = 0ull;

#pragma unroll 1
        for (int ci = 0; ci < CIN; ci++) {
            const float* cb = xbase + ci * 262144 + d0 * 4096;

            // kh UNROLLED: 3 bodies with compile-time kh*64 offsets.
#pragma unroll
            for (int kh = 0; kh < 3; kh++) {
                const float* rp0 = cb + kh * 64;

                // 6 input-depth rows cover kd(0..2) x depth-tile(0..3)
                ull xr[6][3];
#pragma unroll
                for (int r = 0; r < 6; r++) {
                    const float* rp = rp0 + r * 4096;
                    xr[r][0] = rep2(rp[0]);
                    xr[r][1] = rep2(rp[1]);
                    xr[r][2] = rep2(rp[2]);
                }

#pragma unroll
                for (int kd = 0; kd < 3; kd++) {
#pragma unroll
                    for (int kw = 0; kw < 3; kw++) {
                        const int pos = ci * 27 + kd * 9 + kh * 3 + kw;
                        const ull* wrow = &wcg[pos * 8];
#pragma unroll
                        for (int pr = 0; pr < 4; pr++) {
                            const ull wv = wrow[pr];
                            fma2(acc[0][pr], xr[kd + 0][kw], wv);
                            fma2(acc[1][pr], xr[kd + 1][kw], wv);
                            fma2(acc[2][pr], xr[kd + 2][kw], wv);
                            fma2(acc[3][pr], xr[kd + 3][kw], wv);
                        }
                    }
                }
            }
        }

#pragma unroll
        for (int d = 0; d < 4; d++)
#pragma unroll
            for (int pr = 0; pr < 4; pr++) {
                const float2 v = unpk(acc[d][pr]);
                mval[2 * pr]     = fminf(mval[2 * pr],     v.x);
                mval[2 * pr + 1] = fminf(mval[2 * pr + 1], v.y);
            }
    }

    // bias + softmax over 16 channels, split across 2 threads (cg 0/1)
    float v[8];
    float mx = -3.402823466e38f;
#pragma unroll
    for (int c = 0; c < 8; c++) {
        v[c] = mval[c] + bsh[cg * 8 + c];
        mx = fmaxf(mx, v[c]);
    }
    sred[cg][wl] = mx;
    __syncthreads();
    mx = fmaxf(sred[0][wl], sred[1][wl]);
    __syncthreads();

    float s = 0.f;
#pragma unroll
    for (int c = 0; c < 8; c++) {
        v[c] = __expf(v[c] - mx);
        s += v[c];
    }
    sred[cg][wl] = s;
    __syncthreads();
    const float inv = 1.0f / (sred[0][wl] + sred[1][wl]);

    if (active) {
        const int hw = h * OW + w;
#pragma unroll
        for (int c = 0; c < 8; c++) {
            out[(size_t)(n * COUT + cg * 8 + c) * (OH * OW) + hw] = v[c] * inv;
        }
    }
}

extern "C" void kernel_launch(void* const* d_in, const int* in_sizes, int n_in,
                              void* d_out, int out_size)
{
    const float* x    = (const float*)d_in[0];  // [16,3,64,64,64]
    const float* wgt  = (const float*)d_in[1];  // [16,3,3,3,3]
    const float* bias = (const float*)d_in[2];  // [16]
    float* out = (float*)d_out;                 // [16,16,62,62]

    dim3 grid(OH, 16);   // (h', n)
    dim3 block(128);     // 64 w-lanes x 2 channel groups
    fused_conv_min_softmax<<<grid, block>>>(x, wgt, bias, out);
}